// round 1
// baseline (speedup 1.0000x reference)
#include <cuda_runtime.h>

#define HEADS 4
#define F 128
#define MAXN 131072

// ---------------- scratch (static device globals: no allocation allowed) ----
__device__ float g_h[(size_t)MAXN * F];    // GEMM output h (both layers)
__device__ float g_x2[(size_t)MAXN * F];   // layer-1 output / layer-2 input
__device__ float g_acc[(size_t)MAXN * F];  // un-normalized aggregation numerator
__device__ float g_as[MAXN * HEADS];       // alpha_src per node/head
__device__ float g_ad[MAXN * HEADS];       // alpha_dst per node/head
__device__ float g_den[MAXN * HEADS];      // softmax denominator (partial)

__device__ __forceinline__ float leaky_exp(float x) {
    float l = x > 0.f ? x : 0.2f * x;   // leaky_relu slope 0.2
    return __expf(l);
}

// vectorized global reduction-add (sm_90+)
__device__ __forceinline__ void red4(float* p, float a, float b, float c, float d) {
    asm volatile("red.global.add.v4.f32 [%0], {%1,%2,%3,%4};"
                 :: "l"(p), "f"(a), "f"(b), "f"(c), "f"(d) : "memory");
}

// ---------------- zero acc + den -------------------------------------------
__global__ void zero_kernel(int N) {
    int i = blockIdx.x * blockDim.x + threadIdx.x;
    if (i < N * F) g_acc[i] = 0.f;
    if (i < N * HEADS) g_den[i] = 0.f;
}

// ---------------- SGEMM: g_h = X @ W,  X:[N,128], W:[128,128] ---------------
__global__ __launch_bounds__(256, 2)
void gemm_kernel(const float* __restrict__ X, const float* __restrict__ Wm, int N) {
    __shared__ float As[32][132];   // [k][m], padded
    __shared__ float Bs[32][128];   // [k][n]
    const int tid = threadIdx.x;
    const int row0 = blockIdx.x * 128;
    const int ty = tid >> 4, tx = tid & 15;
    const int m0 = ty * 8, n0 = tx * 8;
    float acc[8][8];
#pragma unroll
    for (int i = 0; i < 8; ++i)
#pragma unroll
        for (int j = 0; j < 8; ++j) acc[i][j] = 0.f;

    for (int ks = 0; ks < 128; ks += 32) {
        // A tile: 128 rows x 32 k, stored transposed
#pragma unroll
        for (int it = 0; it < 4; ++it) {
            int idx = it * 256 + tid;
            int m = idx >> 3;          // 0..127
            int q = idx & 7;           // which float4 of the 32-k slab
            int gr = row0 + m;
            float4 v = make_float4(0.f, 0.f, 0.f, 0.f);
            if (gr < N) v = *(const float4*)&X[(size_t)gr * F + ks + q * 4];
            As[q * 4 + 0][m] = v.x; As[q * 4 + 1][m] = v.y;
            As[q * 4 + 2][m] = v.z; As[q * 4 + 3][m] = v.w;
        }
        // B tile: 32 k x 128 n, direct copy
#pragma unroll
        for (int it = 0; it < 4; ++it) {
            int idx = it * 256 + tid;
            int k = idx >> 5;
            int n4 = idx & 31;
            *(float4*)&Bs[k][n4 * 4] = *(const float4*)&Wm[(size_t)(ks + k) * F + n4 * 4];
        }
        __syncthreads();
#pragma unroll
        for (int k = 0; k < 32; ++k) {
            float a[8], b[8];
            *(float4*)(a)     = *(float4*)&As[k][m0];
            *(float4*)(a + 4) = *(float4*)&As[k][m0 + 4];
            *(float4*)(b)     = *(float4*)&Bs[k][n0];
            *(float4*)(b + 4) = *(float4*)&Bs[k][n0 + 4];
#pragma unroll
            for (int i = 0; i < 8; ++i)
#pragma unroll
                for (int j = 0; j < 8; ++j)
                    acc[i][j] = fmaf(a[i], b[j], acc[i][j]);
        }
        __syncthreads();
    }
#pragma unroll
    for (int i = 0; i < 8; ++i) {
        int gr = row0 + m0 + i;
        if (gr < N) {
            *(float4*)&g_h[(size_t)gr * F + n0]     = *(float4*)&acc[i][0];
            *(float4*)&g_h[(size_t)gr * F + n0 + 4] = *(float4*)&acc[i][4];
        }
    }
}

// ---------------- per-node attention logits (warp per node) ----------------
__global__ void alphas_kernel(const float* __restrict__ a_s,
                              const float* __restrict__ a_d, int N) {
    int n = (blockIdx.x * blockDim.x + threadIdx.x) >> 5;
    int lane = threadIdx.x & 31;
    if (n >= N) return;
    float4 hv = *(const float4*)&g_h[(size_t)n * F + lane * 4];
    float4 s4 = *(const float4*)&a_s[lane * 4];
    float4 d4 = *(const float4*)&a_d[lane * 4];
    float ss = hv.x * s4.x + hv.y * s4.y + hv.z * s4.z + hv.w * s4.w;
    float sd = hv.x * d4.x + hv.y * d4.y + hv.z * d4.z + hv.w * d4.w;
    // reduce within each 8-lane head group
#pragma unroll
    for (int off = 4; off >= 1; off >>= 1) {
        ss += __shfl_xor_sync(0xffffffffu, ss, off);
        sd += __shfl_xor_sync(0xffffffffu, sd, off);
    }
    if ((lane & 7) == 0) {
        g_as[n * HEADS + (lane >> 3)] = ss;
        g_ad[n * HEADS + (lane >> 3)] = sd;
    }
}

// ---------------- edge pass (warp per edge) --------------------------------
__global__ void edge_kernel(const int* __restrict__ ei, int E) {
    int gw = (blockIdx.x * blockDim.x + threadIdx.x) >> 5;
    int lane = threadIdx.x & 31;
    if (gw >= E) return;
    int s = __ldg(ei + gw);
    int d = __ldg(ei + E + gw);
    float4 a = *(const float4*)&g_as[s * HEADS];
    float4 b = *(const float4*)&g_ad[d * HEADS];
    float w0 = leaky_exp(a.x + b.x);
    float w1 = leaky_exp(a.y + b.y);
    float w2 = leaky_exp(a.z + b.z);
    float w3 = leaky_exp(a.w + b.w);
    if (lane == 0) red4(&g_den[d * HEADS], w0, w1, w2, w3);
    float wh = lane < 16 ? (lane < 8 ? w0 : w1) : (lane < 24 ? w2 : w3);
    float4 hv = *(const float4*)&g_h[(size_t)s * F + lane * 4];
    red4(&g_acc[(size_t)d * F + lane * 4],
         hv.x * wh, hv.y * wh, hv.z * wh, hv.w * wh);
}

// ---------------- finalize (warp per node): self-loop + normalize + bias ----
template <int LAYER>
__global__ void finalize_kernel(const float* __restrict__ bias,
                                float* __restrict__ out, int N, int write_splits) {
    int n = (blockIdx.x * blockDim.x + threadIdx.x) >> 5;
    int lane = threadIdx.x & 31;
    if (n >= N) return;
    int head = lane >> 3;
    float ws = leaky_exp(g_as[n * HEADS + head] + g_ad[n * HEADS + head]);
    float inv = 1.f / (g_den[n * HEADS + head] + ws + 1e-16f);
    int c = lane * 4;
    float4 acc = *(const float4*)&g_acc[(size_t)n * F + c];
    float4 hv  = *(const float4*)&g_h[(size_t)n * F + c];
    float4 bb  = *(const float4*)&bias[c];
    float4 v;
    v.x = (acc.x + ws * hv.x) * inv + bb.x;
    v.y = (acc.y + ws * hv.y) * inv + bb.y;
    v.z = (acc.z + ws * hv.z) * inv + bb.z;
    v.w = (acc.w + ws * hv.w) * inv + bb.w;
    if (LAYER == 1) {
        v.x = v.x > 0.f ? v.x : expm1f(v.x);
        v.y = v.y > 0.f ? v.y : expm1f(v.y);
        v.z = v.z > 0.f ? v.z : expm1f(v.z);
        v.w = v.w > 0.f ? v.w : expm1f(v.w);
        *(float4*)&g_x2[(size_t)n * F + c] = v;
    } else {
        *(float4*)&out[(size_t)n * F + c] = v;
        if (write_splits) {
            int off = c & 31;  // position within head
            *(float4*)&out[(size_t)N * F + (size_t)head * N * 32 + (size_t)n * 32 + off] = v;
        }
    }
}

// ---------------- launch ----------------------------------------------------
extern "C" void kernel_launch(void* const* d_in, const int* in_sizes, int n_in,
                              void* d_out, int out_size) {
    const float* x   = (const float*)d_in[0];
    const int*   ei  = (const int*)d_in[1];
    const float* W1  = (const float*)d_in[2];
    const float* as1 = (const float*)d_in[3];
    const float* ad1 = (const float*)d_in[4];
    const float* b1  = (const float*)d_in[5];
    const float* W2  = (const float*)d_in[6];
    const float* as2 = (const float*)d_in[7];
    const float* ad2 = (const float*)d_in[8];
    const float* b2  = (const float*)d_in[9];

    int N = in_sizes[0] / F;
    int E = in_sizes[1] / 2;
    float* out = (float*)d_out;
    int write_splits = (out_size >= N * F * 2) ? 1 : 0;

    float* p_x2 = nullptr;
    cudaGetSymbolAddress((void**)&p_x2, g_x2);

    int zb = (N * F + 255) / 256;
    int gb = (N + 127) / 128;
    int wb = (N * 32 + 255) / 256;   // warp-per-node kernels
    int eb = (E + 7) / 8;            // warp-per-edge

    // ---- layer 1 ----
    zero_kernel<<<zb, 256>>>(N);
    gemm_kernel<<<gb, 256>>>(x, W1, N);
    alphas_kernel<<<wb, 256>>>(as1, ad1, N);
    edge_kernel<<<eb, 256>>>(ei, E);
    finalize_kernel<1><<<wb, 256>>>(b1, out, N, 0);

    // ---- layer 2 ----
    zero_kernel<<<zb, 256>>>(N);
    gemm_kernel<<<gb, 256>>>(p_x2, W2, N);
    alphas_kernel<<<wb, 256>>>(as2, ad2, N);
    edge_kernel<<<eb, 256>>>(ei, E);
    finalize_kernel<2><<<wb, 256>>>(b2, out, N, write_splits);
}

// round 2
// speedup vs baseline: 2.1360x; 2.1360x over previous
#include <cuda_runtime.h>

#define HEADS 4
#define F 128
#define MAXN 131072
#define MAXE 2097152

// ---------------- scratch (static device globals) ---------------------------
__device__ float g_h[(size_t)MAXN * F];    // GEMM output h (both layers)
__device__ float g_x2[(size_t)MAXN * F];   // layer-1 output / layer-2 input
__device__ float g_as[MAXN * HEADS];       // alpha_src per node/head
__device__ float g_ad[MAXN * HEADS];       // alpha_dst per node/head
__device__ int   g_deg[MAXN];              // in-degree per node
__device__ int   g_rowptr[MAXN];           // exclusive scan of deg
__device__ int   g_cursor[MAXN];           // scatter cursors
__device__ int   g_blksum[256];            // scan partials
__device__ int   g_blkoff[256];
__device__ int   g_csr_src[MAXE];          // src ids grouped by dst

__device__ __forceinline__ float leaky_exp(float x) {
    float l = x > 0.f ? x : 0.2f * x;
    return __expf(l);
}

// ---------------- CSR build -------------------------------------------------
__global__ void zero_deg_kernel(int N) {
    int i = blockIdx.x * blockDim.x + threadIdx.x;
    if (i < N) g_deg[i] = 0;
}

__global__ void deg_kernel(const int* __restrict__ ei, int E) {
    int i = blockIdx.x * blockDim.x + threadIdx.x;
    if (i < E) atomicAdd(&g_deg[__ldg(ei + E + i)], 1);
}

// block-level inclusive scan (1024/block) -> exclusive rowptr, block sums
__global__ void scan1_kernel(int N) {
    __shared__ int warp_sums[32];
    int t = threadIdx.x, b = blockIdx.x;
    int i = b * 1024 + t;
    int v = (i < N) ? g_deg[i] : 0;
    int x = v;
    // warp inclusive scan
#pragma unroll
    for (int off = 1; off < 32; off <<= 1) {
        int y = __shfl_up_sync(0xffffffffu, x, off);
        if ((t & 31) >= off) x += y;
    }
    if ((t & 31) == 31) warp_sums[t >> 5] = x;
    __syncthreads();
    if (t < 32) {
        int w = warp_sums[t];
#pragma unroll
        for (int off = 1; off < 32; off <<= 1) {
            int y = __shfl_up_sync(0xffffffffu, w, off);
            if (t >= off) w += y;
        }
        warp_sums[t] = w;
    }
    __syncthreads();
    int incl = x + ((t >> 5) ? warp_sums[(t >> 5) - 1] : 0);
    if (i < N) g_rowptr[i] = incl - v;          // exclusive within block
    if (t == 1023) g_blksum[b] = incl;
}

__global__ void scan2_kernel(int nb) {
    int t = threadIdx.x;                         // one block, 128 threads
    int v = (t < nb) ? g_blksum[t] : 0;
    int x = v;
#pragma unroll
    for (int off = 1; off < 32; off <<= 1) {
        int y = __shfl_up_sync(0xffffffffu, x, off);
        if ((t & 31) >= off) x += y;
    }
    __shared__ int ws[4];
    if ((t & 31) == 31) ws[t >> 5] = x;
    __syncthreads();
    int base = 0;
#pragma unroll
    for (int w = 0; w < 4; ++w) if (w < (t >> 5)) base += ws[w];
    if (t < nb) g_blkoff[t] = base + x - v;      // exclusive across blocks
}

__global__ void scan3_kernel(int N) {
    int i = blockIdx.x * blockDim.x + threadIdx.x;
    if (i < N) {
        int r = g_rowptr[i] + g_blkoff[i >> 10];
        g_rowptr[i] = r;
        g_cursor[i] = r;
    }
}

__global__ void scatter_kernel(const int* __restrict__ ei, int E) {
    int i = blockIdx.x * blockDim.x + threadIdx.x;
    if (i >= E) return;
    int s = __ldg(ei + i);
    int d = __ldg(ei + E + i);
    int pos = atomicAdd(&g_cursor[d], 1);
    g_csr_src[pos] = s;
}

// ---------------- SGEMM: g_h = X @ W,  X:[N,128], W:[128,128] ---------------
__global__ __launch_bounds__(256, 2)
void gemm_kernel(const float* __restrict__ X, const float* __restrict__ Wm, int N) {
    __shared__ float As[32][132];
    __shared__ float Bs[32][128];
    const int tid = threadIdx.x;
    const int row0 = blockIdx.x * 128;
    const int ty = tid >> 4, tx = tid & 15;
    const int m0 = ty * 8, n0 = tx * 8;
    float acc[8][8];
#pragma unroll
    for (int i = 0; i < 8; ++i)
#pragma unroll
        for (int j = 0; j < 8; ++j) acc[i][j] = 0.f;

    for (int ks = 0; ks < 128; ks += 32) {
#pragma unroll
        for (int it = 0; it < 4; ++it) {
            int idx = it * 256 + tid;
            int m = idx >> 3, q = idx & 7;
            int gr = row0 + m;
            float4 v = make_float4(0.f, 0.f, 0.f, 0.f);
            if (gr < N) v = *(const float4*)&X[(size_t)gr * F + ks + q * 4];
            As[q * 4 + 0][m] = v.x; As[q * 4 + 1][m] = v.y;
            As[q * 4 + 2][m] = v.z; As[q * 4 + 3][m] = v.w;
        }
#pragma unroll
        for (int it = 0; it < 4; ++it) {
            int idx = it * 256 + tid;
            int k = idx >> 5, n4 = idx & 31;
            *(float4*)&Bs[k][n4 * 4] = *(const float4*)&Wm[(size_t)(ks + k) * F + n4 * 4];
        }
        __syncthreads();
#pragma unroll
        for (int k = 0; k < 32; ++k) {
            float a[8], b[8];
            *(float4*)(a)     = *(float4*)&As[k][m0];
            *(float4*)(a + 4) = *(float4*)&As[k][m0 + 4];
            *(float4*)(b)     = *(float4*)&Bs[k][n0];
            *(float4*)(b + 4) = *(float4*)&Bs[k][n0 + 4];
#pragma unroll
            for (int i = 0; i < 8; ++i)
#pragma unroll
                for (int j = 0; j < 8; ++j)
                    acc[i][j] = fmaf(a[i], b[j], acc[i][j]);
        }
        __syncthreads();
    }
#pragma unroll
    for (int i = 0; i < 8; ++i) {
        int gr = row0 + m0 + i;
        if (gr < N) {
            *(float4*)&g_h[(size_t)gr * F + n0]     = *(float4*)&acc[i][0];
            *(float4*)&g_h[(size_t)gr * F + n0 + 4] = *(float4*)&acc[i][4];
        }
    }
}

// ---------------- per-node attention logits (warp per node) ----------------
__global__ void alphas_kernel(const float* __restrict__ a_s,
                              const float* __restrict__ a_d, int N) {
    int n = (blockIdx.x * blockDim.x + threadIdx.x) >> 5;
    int lane = threadIdx.x & 31;
    if (n >= N) return;
    float4 hv = *(const float4*)&g_h[(size_t)n * F + lane * 4];
    float4 s4 = *(const float4*)&a_s[lane * 4];
    float4 d4 = *(const float4*)&a_d[lane * 4];
    float ss = hv.x * s4.x + hv.y * s4.y + hv.z * s4.z + hv.w * s4.w;
    float sd = hv.x * d4.x + hv.y * d4.y + hv.z * d4.z + hv.w * d4.w;
#pragma unroll
    for (int off = 4; off >= 1; off >>= 1) {
        ss += __shfl_xor_sync(0xffffffffu, ss, off);
        sd += __shfl_xor_sync(0xffffffffu, sd, off);
    }
    if ((lane & 7) == 0) {
        g_as[n * HEADS + (lane >> 3)] = ss;
        g_ad[n * HEADS + (lane >> 3)] = sd;
    }
}

// ---------------- CSR aggregation (warp per dst node) -----------------------
// accumulates numerator + denominator in registers; epilogue: self-loop,
// normalize, bias, (ELU layer1 | splits layer2)
template <int LAYER>
__global__ void aggregate_kernel(const float* __restrict__ bias,
                                 float* __restrict__ out, int N, int write_splits) {
    int n = (blockIdx.x * blockDim.x + threadIdx.x) >> 5;
    int lane = threadIdx.x & 31;
    if (n >= N) return;
    int head = lane >> 3;
    int c = lane * 4;

    float adh = __ldg(&g_ad[n * HEADS + head]);
    float4 acc = make_float4(0.f, 0.f, 0.f, 0.f);
    float den = 0.f;

    int e = g_rowptr[n];
    int end = e + g_deg[n];

    // 2-way software-pipelined gather loop
    for (; e + 2 <= end; e += 2) {
        int s0 = __ldg(&g_csr_src[e]);
        int s1 = __ldg(&g_csr_src[e + 1]);
        float as0 = __ldg(&g_as[s0 * HEADS + head]);
        float as1 = __ldg(&g_as[s1 * HEADS + head]);
        float4 h0 = *(const float4*)&g_h[(size_t)s0 * F + c];
        float4 h1 = *(const float4*)&g_h[(size_t)s1 * F + c];
        float w0 = leaky_exp(as0 + adh);
        float w1 = leaky_exp(as1 + adh);
        den += w0 + w1;
        acc.x = fmaf(w0, h0.x, fmaf(w1, h1.x, acc.x));
        acc.y = fmaf(w0, h0.y, fmaf(w1, h1.y, acc.y));
        acc.z = fmaf(w0, h0.z, fmaf(w1, h1.z, acc.z));
        acc.w = fmaf(w0, h0.w, fmaf(w1, h1.w, acc.w));
    }
    if (e < end) {
        int s0 = __ldg(&g_csr_src[e]);
        float as0 = __ldg(&g_as[s0 * HEADS + head]);
        float4 h0 = *(const float4*)&g_h[(size_t)s0 * F + c];
        float w0 = leaky_exp(as0 + adh);
        den += w0;
        acc.x = fmaf(w0, h0.x, acc.x);
        acc.y = fmaf(w0, h0.y, acc.y);
        acc.z = fmaf(w0, h0.z, acc.z);
        acc.w = fmaf(w0, h0.w, acc.w);
    }

    // self-loop
    float ws = leaky_exp(__ldg(&g_as[n * HEADS + head]) + adh);
    float4 hv = *(const float4*)&g_h[(size_t)n * F + c];
    den += ws;
    acc.x = fmaf(ws, hv.x, acc.x);
    acc.y = fmaf(ws, hv.y, acc.y);
    acc.z = fmaf(ws, hv.z, acc.z);
    acc.w = fmaf(ws, hv.w, acc.w);

    float inv = 1.f / (den + 1e-16f);
    float4 bb = *(const float4*)&bias[c];
    float4 v;
    v.x = acc.x * inv + bb.x;
    v.y = acc.y * inv + bb.y;
    v.z = acc.z * inv + bb.z;
    v.w = acc.w * inv + bb.w;

    if (LAYER == 1) {
        v.x = v.x > 0.f ? v.x : expm1f(v.x);
        v.y = v.y > 0.f ? v.y : expm1f(v.y);
        v.z = v.z > 0.f ? v.z : expm1f(v.z);
        v.w = v.w > 0.f ? v.w : expm1f(v.w);
        *(float4*)&g_x2[(size_t)n * F + c] = v;
    } else {
        *(float4*)&out[(size_t)n * F + c] = v;
        if (write_splits) {
            int off = c & 31;
            *(float4*)&out[(size_t)N * F + (size_t)head * N * 32 + (size_t)n * 32 + off] = v;
        }
    }
}

// ---------------- launch ----------------------------------------------------
extern "C" void kernel_launch(void* const* d_in, const int* in_sizes, int n_in,
                              void* d_out, int out_size) {
    const float* x   = (const float*)d_in[0];
    const int*   ei  = (const int*)d_in[1];
    const float* W1  = (const float*)d_in[2];
    const float* as1 = (const float*)d_in[3];
    const float* ad1 = (const float*)d_in[4];
    const float* b1  = (const float*)d_in[5];
    const float* W2  = (const float*)d_in[6];
    const float* as2 = (const float*)d_in[7];
    const float* ad2 = (const float*)d_in[8];
    const float* b2  = (const float*)d_in[9];

    int N = in_sizes[0] / F;
    int E = in_sizes[1] / 2;
    float* out = (float*)d_out;
    int write_splits = (out_size >= N * F * 2) ? 1 : 0;

    float* p_x2 = nullptr;
    cudaGetSymbolAddress((void**)&p_x2, g_x2);

    int gb = (N + 127) / 128;
    int wb = (N * 32 + 255) / 256;       // warp-per-node kernels
    int nb1024 = (N + 1023) / 1024;      // scan blocks

    // ---- CSR build (once, shared by both layers) ----
    zero_deg_kernel<<<(N + 255) / 256, 256>>>(N);
    deg_kernel<<<(E + 255) / 256, 256>>>(ei, E);
    scan1_kernel<<<nb1024, 1024>>>(N);
    scan2_kernel<<<1, 128>>>(nb1024);
    scan3_kernel<<<(N + 255) / 256, 256>>>(N);
    scatter_kernel<<<(E + 255) / 256, 256>>>(ei, E);

    // ---- layer 1 ----
    gemm_kernel<<<gb, 256>>>(x, W1, N);
    alphas_kernel<<<wb, 256>>>(as1, ad1, N);
    aggregate_kernel<1><<<wb, 256>>>(b1, out, N, 0);

    // ---- layer 2 ----
    gemm_kernel<<<gb, 256>>>(p_x2, W2, N);
    alphas_kernel<<<wb, 256>>>(as2, ad2, N);
    aggregate_kernel<2><<<wb, 256>>>(b2, out, N, write_splits);
}

// round 3
// speedup vs baseline: 3.0766x; 1.4403x over previous
#include <cuda_runtime.h>
#include <cstdint>

#define HEADS 4
#define F 128
#define MAXN 131072
#define MAXE 2097152
#define XS_STRIDE 132
#define WS_STRIDE 136

// ---------------- scratch (static device globals) ---------------------------
__device__ float g_h[(size_t)MAXN * F];    // GEMM output h (both layers)
__device__ float g_x2[(size_t)MAXN * F];   // layer-1 output / layer-2 input
__device__ float g_as[MAXN * HEADS];       // alpha_src per node/head
__device__ float g_ad[MAXN * HEADS];       // alpha_dst per node/head
__device__ int   g_deg[MAXN];
__device__ int   g_rowptr[MAXN];
__device__ int   g_cursor[MAXN];
__device__ int   g_blksum[256];
__device__ int   g_blkoff[256];
__device__ int   g_csr_src[MAXE];

__device__ __forceinline__ float leaky_exp(float x) {
    float l = x > 0.f ? x : 0.2f * x;
    return __expf(l);
}

// ---------------- CSR build -------------------------------------------------
__global__ void zero_deg_kernel(int N) {
    int i = blockIdx.x * blockDim.x + threadIdx.x;
    if (i < N) g_deg[i] = 0;
}

__global__ void deg_kernel(const int* __restrict__ ei, int E) {
    int i = blockIdx.x * blockDim.x + threadIdx.x;
    if (i < E) atomicAdd(&g_deg[__ldg(ei + E + i)], 1);
}

__global__ void scan1_kernel(int N) {
    __shared__ int warp_sums[32];
    int t = threadIdx.x, b = blockIdx.x;
    int i = b * 1024 + t;
    int v = (i < N) ? g_deg[i] : 0;
    int x = v;
#pragma unroll
    for (int off = 1; off < 32; off <<= 1) {
        int y = __shfl_up_sync(0xffffffffu, x, off);
        if ((t & 31) >= off) x += y;
    }
    if ((t & 31) == 31) warp_sums[t >> 5] = x;
    __syncthreads();
    if (t < 32) {
        int w = warp_sums[t];
#pragma unroll
        for (int off = 1; off < 32; off <<= 1) {
            int y = __shfl_up_sync(0xffffffffu, w, off);
            if (t >= off) w += y;
        }
        warp_sums[t] = w;
    }
    __syncthreads();
    int incl = x + ((t >> 5) ? warp_sums[(t >> 5) - 1] : 0);
    if (i < N) g_rowptr[i] = incl - v;
    if (t == 1023) g_blksum[b] = incl;
}

__global__ void scan2_kernel(int nb) {
    int t = threadIdx.x;
    int v = (t < nb) ? g_blksum[t] : 0;
    int x = v;
#pragma unroll
    for (int off = 1; off < 32; off <<= 1) {
        int y = __shfl_up_sync(0xffffffffu, x, off);
        if ((t & 31) >= off) x += y;
    }
    __shared__ int ws[4];
    if ((t & 31) == 31) ws[t >> 5] = x;
    __syncthreads();
    int base = 0;
#pragma unroll
    for (int w = 0; w < 4; ++w) if (w < (t >> 5)) base += ws[w];
    if (t < nb) g_blkoff[t] = base + x - v;
}

__global__ void scan3_kernel(int N) {
    int i = blockIdx.x * blockDim.x + threadIdx.x;
    if (i < N) {
        int r = g_rowptr[i] + g_blkoff[i >> 10];
        g_rowptr[i] = r;
        g_cursor[i] = r;
    }
}

__global__ void scatter_kernel(const int* __restrict__ ei, int E) {
    int i = blockIdx.x * blockDim.x + threadIdx.x;
    if (i >= E) return;
    int s = __ldg(ei + i);
    int d = __ldg(ei + E + i);
    int pos = atomicAdd(&g_cursor[d], 1);
    g_csr_src[pos] = s;
}

// ---------------- tf32 tensor-core GEMM + fused alpha epilogue --------------
// h = X @ W (N x 128 @ 128 x 128); also alpha_src/dst per node/head.
// block: 256 thr, tile 128 rows x 128 cols, whole K=128 staged in smem.
// warp (w): rows (w>>1)*32..+31, cols (w&1)*64..+63  (2 m-tiles x 8 n-tiles)
__global__ void __launch_bounds__(256, 1)
gemm_tf32_kernel(const float* __restrict__ X, const float* __restrict__ Wm,
                 const float* __restrict__ a_s, const float* __restrict__ a_d,
                 int N) {
    extern __shared__ float smem[];
    float* Xs = smem;                       // [128][XS_STRIDE]
    float* Ws = smem + 128 * XS_STRIDE;     // [128][WS_STRIDE]
    const int tid = threadIdx.x;
    const int row0 = blockIdx.x * 128;

    // ---- fill tiles (with rna rounding to tf32) ----
#pragma unroll
    for (int it = 0; it < 16; ++it) {
        int idx = it * 256 + tid;        // 0..4095
        int r = idx >> 5;                // 0..127
        int q = idx & 31;                // float4 index within row
        int gr = row0 + r;
        float4 v = make_float4(0.f, 0.f, 0.f, 0.f);
        if (gr < N) v = *(const float4*)&X[(size_t)gr * F + q * 4];
        uint32_t u0, u1, u2, u3;
        asm("cvt.rna.tf32.f32 %0, %1;" : "=r"(u0) : "f"(v.x));
        asm("cvt.rna.tf32.f32 %0, %1;" : "=r"(u1) : "f"(v.y));
        asm("cvt.rna.tf32.f32 %0, %1;" : "=r"(u2) : "f"(v.z));
        asm("cvt.rna.tf32.f32 %0, %1;" : "=r"(u3) : "f"(v.w));
        float4 sv = make_float4(__uint_as_float(u0), __uint_as_float(u1),
                                __uint_as_float(u2), __uint_as_float(u3));
        *(float4*)&Xs[r * XS_STRIDE + q * 4] = sv;

        float4 wv = *(const float4*)&Wm[idx * 4];
        asm("cvt.rna.tf32.f32 %0, %1;" : "=r"(u0) : "f"(wv.x));
        asm("cvt.rna.tf32.f32 %0, %1;" : "=r"(u1) : "f"(wv.y));
        asm("cvt.rna.tf32.f32 %0, %1;" : "=r"(u2) : "f"(wv.z));
        asm("cvt.rna.tf32.f32 %0, %1;" : "=r"(u3) : "f"(wv.w));
        float4 swv = make_float4(__uint_as_float(u0), __uint_as_float(u1),
                                 __uint_as_float(u2), __uint_as_float(u3));
        *(float4*)&Ws[r * WS_STRIDE + q * 4] = swv;
    }
    __syncthreads();

    const int w = tid >> 5, lane = tid & 31;
    const int g = lane >> 2, q = lane & 3;
    const int mrow = (w >> 1) * 32;         // local row base of this warp
    const int cb = (w & 1) * 64;            // col base of this warp

    float acc[2][8][4];
#pragma unroll
    for (int mt = 0; mt < 2; ++mt)
#pragma unroll
        for (int j = 0; j < 8; ++j)
#pragma unroll
            for (int t = 0; t < 4; ++t) acc[mt][j][t] = 0.f;

    const uint32_t* Xu = (const uint32_t*)Xs;
    const uint32_t* Wu = (const uint32_t*)Ws;

#pragma unroll
    for (int kk = 0; kk < 16; ++kk) {
        int k0 = kk * 8;
        uint32_t a[2][4];
#pragma unroll
        for (int mt = 0; mt < 2; ++mt) {
            int rb = mrow + mt * 16 + g;
            a[mt][0] = Xu[rb * XS_STRIDE + k0 + q];
            a[mt][1] = Xu[(rb + 8) * XS_STRIDE + k0 + q];
            a[mt][2] = Xu[rb * XS_STRIDE + k0 + q + 4];
            a[mt][3] = Xu[(rb + 8) * XS_STRIDE + k0 + q + 4];
        }
#pragma unroll
        for (int j = 0; j < 8; ++j) {
            uint32_t b0 = Wu[(k0 + q) * WS_STRIDE + cb + j * 8 + g];
            uint32_t b1 = Wu[(k0 + q + 4) * WS_STRIDE + cb + j * 8 + g];
#pragma unroll
            for (int mt = 0; mt < 2; ++mt) {
                asm volatile(
                    "mma.sync.aligned.m16n8k8.row.col.f32.tf32.tf32.f32 "
                    "{%0,%1,%2,%3}, {%4,%5,%6,%7}, {%8,%9}, {%0,%1,%2,%3};"
                    : "+f"(acc[mt][j][0]), "+f"(acc[mt][j][1]),
                      "+f"(acc[mt][j][2]), "+f"(acc[mt][j][3])
                    : "r"(a[mt][0]), "r"(a[mt][1]), "r"(a[mt][2]), "r"(a[mt][3]),
                      "r"(b0), "r"(b1));
            }
        }
    }

    // ---- epilogue: store h (float2 per tile-row) + fused alpha partials ----
    float pa[4][2] = {{0.f, 0.f}, {0.f, 0.f}, {0.f, 0.f}, {0.f, 0.f}};
    float pd[4][2] = {{0.f, 0.f}, {0.f, 0.f}, {0.f, 0.f}, {0.f, 0.f}};
#pragma unroll
    for (int mt = 0; mt < 2; ++mt) {
#pragma unroll
        for (int j = 0; j < 8; ++j) {
            int col = cb + j * 8 + q * 2;
            float as0 = __ldg(&a_s[col]), as1 = __ldg(&a_s[col + 1]);
            float ad0 = __ldg(&a_d[col]), ad1 = __ldg(&a_d[col + 1]);
            int hh = j >> 2;                 // head within this warp's group
            float2 lo = make_float2(acc[mt][j][0], acc[mt][j][1]);  // row g
            float2 hi = make_float2(acc[mt][j][2], acc[mt][j][3]);  // row g+8
            pa[mt * 2 + 0][hh] += lo.x * as0 + lo.y * as1;
            pd[mt * 2 + 0][hh] += lo.x * ad0 + lo.y * ad1;
            pa[mt * 2 + 1][hh] += hi.x * as0 + hi.y * as1;
            pd[mt * 2 + 1][hh] += hi.x * ad0 + hi.y * ad1;
            int r_lo = row0 + mrow + mt * 16 + g;
            if (r_lo < N) *(float2*)&g_h[(size_t)r_lo * F + col] = lo;
            if (r_lo + 8 < N) *(float2*)&g_h[(size_t)(r_lo + 8) * F + col] = hi;
        }
    }
    // quad reduction (lanes sharing groupID)
#pragma unroll
    for (int off = 1; off <= 2; off <<= 1) {
#pragma unroll
        for (int s = 0; s < 4; ++s)
#pragma unroll
            for (int hh = 0; hh < 2; ++hh) {
                pa[s][hh] += __shfl_xor_sync(0xffffffffu, pa[s][hh], off);
                pd[s][hh] += __shfl_xor_sync(0xffffffffu, pd[s][hh], off);
            }
    }
    if (q == 0) {
        int head_base = (w & 1) * 2;
#pragma unroll
        for (int s = 0; s < 4; ++s) {
            int mt = s >> 1, rh = s & 1;
            int row = row0 + mrow + mt * 16 + rh * 8 + g;
            if (row < N) {
#pragma unroll
                for (int hh = 0; hh < 2; ++hh) {
                    g_as[row * HEADS + head_base + hh] = pa[s][hh];
                    g_ad[row * HEADS + head_base + hh] = pd[s][hh];
                }
            }
        }
    }
}

// ---------------- CSR aggregation (warp per dst node) -----------------------
template <int LAYER>
__global__ void aggregate_kernel(const float* __restrict__ bias,
                                 float* __restrict__ out, int N, int write_splits) {
    int n = (blockIdx.x * blockDim.x + threadIdx.x) >> 5;
    int lane = threadIdx.x & 31;
    if (n >= N) return;
    int head = lane >> 3;
    int c = lane * 4;

    float adh = __ldg(&g_ad[n * HEADS + head]);
    float4 acc = make_float4(0.f, 0.f, 0.f, 0.f);
    float den = 0.f;

    int e = g_rowptr[n];
    int end = e + g_deg[n];

    for (; e + 2 <= end; e += 2) {
        int s0 = __ldg(&g_csr_src[e]);
        int s1 = __ldg(&g_csr_src[e + 1]);
        float as0 = __ldg(&g_as[s0 * HEADS + head]);
        float as1 = __ldg(&g_as[s1 * HEADS + head]);
        float4 h0 = *(const float4*)&g_h[(size_t)s0 * F + c];
        float4 h1 = *(const float4*)&g_h[(size_t)s1 * F + c];
        float w0 = leaky_exp(as0 + adh);
        float w1 = leaky_exp(as1 + adh);
        den += w0 + w1;
        acc.x = fmaf(w0, h0.x, fmaf(w1, h1.x, acc.x));
        acc.y = fmaf(w0, h0.y, fmaf(w1, h1.y, acc.y));
        acc.z = fmaf(w0, h0.z, fmaf(w1, h1.z, acc.z));
        acc.w = fmaf(w0, h0.w, fmaf(w1, h1.w, acc.w));
    }
    if (e < end) {
        int s0 = __ldg(&g_csr_src[e]);
        float as0 = __ldg(&g_as[s0 * HEADS + head]);
        float4 h0 = *(const float4*)&g_h[(size_t)s0 * F + c];
        float w0 = leaky_exp(as0 + adh);
        den += w0;
        acc.x = fmaf(w0, h0.x, acc.x);
        acc.y = fmaf(w0, h0.y, acc.y);
        acc.z = fmaf(w0, h0.z, acc.z);
        acc.w = fmaf(w0, h0.w, acc.w);
    }

    // self-loop
    float ws = leaky_exp(__ldg(&g_as[n * HEADS + head]) + adh);
    float4 hv = *(const float4*)&g_h[(size_t)n * F + c];
    den += ws;
    acc.x = fmaf(ws, hv.x, acc.x);
    acc.y = fmaf(ws, hv.y, acc.y);
    acc.z = fmaf(ws, hv.z, acc.z);
    acc.w = fmaf(ws, hv.w, acc.w);

    float inv = 1.f / (den + 1e-16f);
    float4 bb = *(const float4*)&bias[c];
    float4 v;
    v.x = acc.x * inv + bb.x;
    v.y = acc.y * inv + bb.y;
    v.z = acc.z * inv + bb.z;
    v.w = acc.w * inv + bb.w;

    if (LAYER == 1) {
        v.x = v.x > 0.f ? v.x : expm1f(v.x);
        v.y = v.y > 0.f ? v.y : expm1f(v.y);
        v.z = v.z > 0.f ? v.z : expm1f(v.z);
        v.w = v.w > 0.f ? v.w : expm1f(v.w);
        *(float4*)&g_x2[(size_t)n * F + c] = v;
    } else {
        *(float4*)&out[(size_t)n * F + c] = v;
        if (write_splits) {
            int off = c & 31;
            *(float4*)&out[(size_t)N * F + (size_t)head * N * 32 + (size_t)n * 32 + off] = v;
        }
    }
}

// ---------------- launch ----------------------------------------------------
extern "C" void kernel_launch(void* const* d_in, const int* in_sizes, int n_in,
                              void* d_out, int out_size) {
    const float* x   = (const float*)d_in[0];
    const int*   ei  = (const int*)d_in[1];
    const float* W1  = (const float*)d_in[2];
    const float* as1 = (const float*)d_in[3];
    const float* ad1 = (const float*)d_in[4];
    const float* b1  = (const float*)d_in[5];
    const float* W2  = (const float*)d_in[6];
    const float* as2 = (const float*)d_in[7];
    const float* ad2 = (const float*)d_in[8];
    const float* b2  = (const float*)d_in[9];

    int N = in_sizes[0] / F;
    int E = in_sizes[1] / 2;
    float* out = (float*)d_out;
    int write_splits = (out_size >= N * F * 2) ? 1 : 0;

    float* p_x2 = nullptr;
    cudaGetSymbolAddress((void**)&p_x2, g_x2);

    const int SMEM_BYTES = (128 * XS_STRIDE + 128 * WS_STRIDE) * 4;
    cudaFuncSetAttribute(gemm_tf32_kernel,
                         cudaFuncAttributeMaxDynamicSharedMemorySize, SMEM_BYTES);

    int gb = (N + 127) / 128;
    int wb = (N * 32 + 255) / 256;
    int nb1024 = (N + 1023) / 1024;

    // ---- CSR build (once, shared by both layers) ----
    zero_deg_kernel<<<(N + 255) / 256, 256>>>(N);
    deg_kernel<<<(E + 255) / 256, 256>>>(ei, E);
    scan1_kernel<<<nb1024, 1024>>>(N);
    scan2_kernel<<<1, 128>>>(nb1024);
    scan3_kernel<<<(N + 255) / 256, 256>>>(N);
    scatter_kernel<<<(E + 255) / 256, 256>>>(ei, E);

    // ---- layer 1 ----
    gemm_tf32_kernel<<<gb, 256, SMEM_BYTES>>>(x, W1, as1, ad1, N);
    aggregate_kernel<1><<<wb, 256>>>(b1, out, N, 0);

    // ---- layer 2 ----
    gemm_tf32_kernel<<<gb, 256, SMEM_BYTES>>>(p_x2, W2, as2, ad2, N);
    aggregate_kernel<2><<<wb, 256>>>(b2, out, N, write_splits);
}

// round 4
// speedup vs baseline: 3.0996x; 1.0075x over previous
#include <cuda_runtime.h>
#include <cuda_fp16.h>
#include <cstdint>

#define HEADS 4
#define F 128
#define MAXN 131072
#define MAXE 2097152
#define XS_STRIDE 132
#define WS_STRIDE 136

// ---------------- scratch (static device globals) ---------------------------
__device__ __half g_h[(size_t)MAXN * F];   // GEMM output h (fp16, both layers)
__device__ __half g_x2[(size_t)MAXN * F];  // layer-1 output / layer-2 input (fp16)
__device__ float g_as[MAXN * HEADS];       // alpha_src per node/head (fp32)
__device__ float g_ad[MAXN * HEADS];       // alpha_dst per node/head (fp32)
__device__ int   g_deg[MAXN];
__device__ int   g_rowptr[MAXN];
__device__ int   g_cursor[MAXN];
__device__ int   g_blksum[256];
__device__ int   g_csr_src[MAXE];

__device__ __forceinline__ float leaky_exp(float x) {
    float l = x > 0.f ? x : 0.2f * x;
    return __expf(l);
}

// load 4 fp16 (8B) -> float4
__device__ __forceinline__ float4 load_h4(const __half* p) {
    uint2 raw = *(const uint2*)p;
    __half2 h0 = *reinterpret_cast<__half2*>(&raw.x);
    __half2 h1 = *reinterpret_cast<__half2*>(&raw.y);
    float2 f0 = __half22float2(h0);
    float2 f1 = __half22float2(h1);
    return make_float4(f0.x, f0.y, f1.x, f1.y);
}

// ---------------- CSR build -------------------------------------------------
__global__ void zero_deg_kernel(int N) {
    int i = blockIdx.x * blockDim.x + threadIdx.x;
    if (i < N) g_deg[i] = 0;
}

__global__ void deg_kernel(const int* __restrict__ ei, int E) {
    int i = blockIdx.x * blockDim.x + threadIdx.x;
    if (i < E) atomicAdd(&g_deg[__ldg(ei + E + i)], 1);
}

// per-1024-block inclusive scan -> exclusive rowptr (within block), block sums
__global__ void scan1_kernel(int N) {
    __shared__ int warp_sums[32];
    int t = threadIdx.x, b = blockIdx.x;
    int i = b * 1024 + t;
    int v = (i < N) ? g_deg[i] : 0;
    int x = v;
#pragma unroll
    for (int off = 1; off < 32; off <<= 1) {
        int y = __shfl_up_sync(0xffffffffu, x, off);
        if ((t & 31) >= off) x += y;
    }
    if ((t & 31) == 31) warp_sums[t >> 5] = x;
    __syncthreads();
    if (t < 32) {
        int w = warp_sums[t];
#pragma unroll
        for (int off = 1; off < 32; off <<= 1) {
            int y = __shfl_up_sync(0xffffffffu, w, off);
            if (t >= off) w += y;
        }
        warp_sums[t] = w;
    }
    __syncthreads();
    int incl = x + ((t >> 5) ? warp_sums[(t >> 5) - 1] : 0);
    if (i < N) g_rowptr[i] = incl - v;
    if (t == 1023) g_blksum[b] = incl;
}

// fused: block offset (re-derived per block from g_blksum) + rowptr fixup
__global__ void scan3_kernel(int N) {
    __shared__ int s_off;
    int b = blockIdx.x, t = threadIdx.x;
    if (t < 32) {
        int sum = 0;
        for (int j = t; j < b; j += 32) sum += g_blksum[j];
#pragma unroll
        for (int off = 16; off; off >>= 1)
            sum += __shfl_xor_sync(0xffffffffu, sum, off);
        if (t == 0) s_off = sum;
    }
    __syncthreads();
    int i = b * 1024 + t;
    if (i < N) {
        int r = g_rowptr[i] + s_off;
        g_rowptr[i] = r;
        g_cursor[i] = r;
    }
}

__global__ void scatter_kernel(const int* __restrict__ ei, int E) {
    int i = blockIdx.x * blockDim.x + threadIdx.x;
    if (i >= E) return;
    int s = __ldg(ei + i);
    int d = __ldg(ei + E + i);
    int pos = atomicAdd(&g_cursor[d], 1);
    g_csr_src[pos] = s;
}

// ---------------- tf32 tensor-core GEMM + fused alpha epilogue --------------
// h = X @ W (N x 128 @ 128 x 128), h stored fp16; alpha from fp32 accumulators.
// templated on input type (layer1: float, layer2: fp16 x2)
template <typename T>
__global__ void __launch_bounds__(256, 1)
gemm_tf32_kernel(const T* __restrict__ X, const float* __restrict__ Wm,
                 const float* __restrict__ a_s, const float* __restrict__ a_d,
                 int N) {
    extern __shared__ float smem[];
    float* Xs = smem;                       // [128][XS_STRIDE]
    float* Ws = smem + 128 * XS_STRIDE;     // [128][WS_STRIDE]
    const int tid = threadIdx.x;
    const int row0 = blockIdx.x * 128;

#pragma unroll
    for (int it = 0; it < 16; ++it) {
        int idx = it * 256 + tid;        // 0..4095
        int r = idx >> 5;                // row 0..127
        int q = idx & 31;                // 4-elem slot
        int gr = row0 + r;
        float4 v = make_float4(0.f, 0.f, 0.f, 0.f);
        if (gr < N) {
            if constexpr (sizeof(T) == 4) {
                v = *(const float4*)&X[(size_t)gr * F + q * 4];
            } else {
                v = load_h4((const __half*)&X[(size_t)gr * F + q * 4]);
            }
        }
        uint32_t u0, u1, u2, u3;
        asm("cvt.rna.tf32.f32 %0, %1;" : "=r"(u0) : "f"(v.x));
        asm("cvt.rna.tf32.f32 %0, %1;" : "=r"(u1) : "f"(v.y));
        asm("cvt.rna.tf32.f32 %0, %1;" : "=r"(u2) : "f"(v.z));
        asm("cvt.rna.tf32.f32 %0, %1;" : "=r"(u3) : "f"(v.w));
        *(float4*)&Xs[r * XS_STRIDE + q * 4] =
            make_float4(__uint_as_float(u0), __uint_as_float(u1),
                        __uint_as_float(u2), __uint_as_float(u3));

        float4 wv = *(const float4*)&Wm[idx * 4];
        asm("cvt.rna.tf32.f32 %0, %1;" : "=r"(u0) : "f"(wv.x));
        asm("cvt.rna.tf32.f32 %0, %1;" : "=r"(u1) : "f"(wv.y));
        asm("cvt.rna.tf32.f32 %0, %1;" : "=r"(u2) : "f"(wv.z));
        asm("cvt.rna.tf32.f32 %0, %1;" : "=r"(u3) : "f"(wv.w));
        *(float4*)&Ws[r * WS_STRIDE + q * 4] =
            make_float4(__uint_as_float(u0), __uint_as_float(u1),
                        __uint_as_float(u2), __uint_as_float(u3));
    }
    __syncthreads();

    const int w = tid >> 5, lane = tid & 31;
    const int g = lane >> 2, q = lane & 3;
    const int mrow = (w >> 1) * 32;
    const int cb = (w & 1) * 64;

    float acc[2][8][4];
#pragma unroll
    for (int mt = 0; mt < 2; ++mt)
#pragma unroll
        for (int j = 0; j < 8; ++j)
#pragma unroll
            for (int t = 0; t < 4; ++t) acc[mt][j][t] = 0.f;

    const uint32_t* Xu = (const uint32_t*)Xs;
    const uint32_t* Wu = (const uint32_t*)Ws;

#pragma unroll
    for (int kk = 0; kk < 16; ++kk) {
        int k0 = kk * 8;
        uint32_t a[2][4];
#pragma unroll
        for (int mt = 0; mt < 2; ++mt) {
            int rb = mrow + mt * 16 + g;
            a[mt][0] = Xu[rb * XS_STRIDE + k0 + q];
            a[mt][1] = Xu[(rb + 8) * XS_STRIDE + k0 + q];
            a[mt][2] = Xu[rb * XS_STRIDE + k0 + q + 4];
            a[mt][3] = Xu[(rb + 8) * XS_STRIDE + k0 + q + 4];
        }
#pragma unroll
        for (int j = 0; j < 8; ++j) {
            uint32_t b0 = Wu[(k0 + q) * WS_STRIDE + cb + j * 8 + g];
            uint32_t b1 = Wu[(k0 + q + 4) * WS_STRIDE + cb + j * 8 + g];
#pragma unroll
            for (int mt = 0; mt < 2; ++mt) {
                asm volatile(
                    "mma.sync.aligned.m16n8k8.row.col.f32.tf32.tf32.f32 "
                    "{%0,%1,%2,%3}, {%4,%5,%6,%7}, {%8,%9}, {%0,%1,%2,%3};"
                    : "+f"(acc[mt][j][0]), "+f"(acc[mt][j][1]),
                      "+f"(acc[mt][j][2]), "+f"(acc[mt][j][3])
                    : "r"(a[mt][0]), "r"(a[mt][1]), "r"(a[mt][2]), "r"(a[mt][3]),
                      "r"(b0), "r"(b1));
            }
        }
    }

    // ---- epilogue: store h as fp16 + fused alpha partials (from fp32 acc) ---
    float pa[4][2] = {{0.f, 0.f}, {0.f, 0.f}, {0.f, 0.f}, {0.f, 0.f}};
    float pd[4][2] = {{0.f, 0.f}, {0.f, 0.f}, {0.f, 0.f}, {0.f, 0.f}};
#pragma unroll
    for (int mt = 0; mt < 2; ++mt) {
#pragma unroll
        for (int j = 0; j < 8; ++j) {
            int col = cb + j * 8 + q * 2;
            float as0 = __ldg(&a_s[col]), as1 = __ldg(&a_s[col + 1]);
            float ad0 = __ldg(&a_d[col]), ad1 = __ldg(&a_d[col + 1]);
            int hh = j >> 2;
            float2 lo = make_float2(acc[mt][j][0], acc[mt][j][1]);  // row g
            float2 hi = make_float2(acc[mt][j][2], acc[mt][j][3]);  // row g+8
            pa[mt * 2 + 0][hh] += lo.x * as0 + lo.y * as1;
            pd[mt * 2 + 0][hh] += lo.x * ad0 + lo.y * ad1;
            pa[mt * 2 + 1][hh] += hi.x * as0 + hi.y * as1;
            pd[mt * 2 + 1][hh] += hi.x * ad0 + hi.y * ad1;
            int r_lo = row0 + mrow + mt * 16 + g;
            if (r_lo < N)
                *(__half2*)&g_h[(size_t)r_lo * F + col] = __floats2half2_rn(lo.x, lo.y);
            if (r_lo + 8 < N)
                *(__half2*)&g_h[(size_t)(r_lo + 8) * F + col] = __floats2half2_rn(hi.x, hi.y);
        }
    }
#pragma unroll
    for (int off = 1; off <= 2; off <<= 1) {
#pragma unroll
        for (int s = 0; s < 4; ++s)
#pragma unroll
            for (int hh = 0; hh < 2; ++hh) {
                pa[s][hh] += __shfl_xor_sync(0xffffffffu, pa[s][hh], off);
                pd[s][hh] += __shfl_xor_sync(0xffffffffu, pd[s][hh], off);
            }
    }
    if (q == 0) {
        int head_base = (w & 1) * 2;
#pragma unroll
        for (int s = 0; s < 4; ++s) {
            int mt = s >> 1, rh = s & 1;
            int row = row0 + mrow + mt * 16 + rh * 8 + g;
            if (row < N) {
#pragma unroll
                for (int hh = 0; hh < 2; ++hh) {
                    g_as[row * HEADS + head_base + hh] = pa[s][hh];
                    g_ad[row * HEADS + head_base + hh] = pd[s][hh];
                }
            }
        }
    }
}

// ---------------- CSR aggregation (warp per dst node, fp16 gather) ----------
template <int LAYER>
__global__ void aggregate_kernel(const float* __restrict__ bias,
                                 float* __restrict__ out, int N, int write_splits) {
    int n = (blockIdx.x * blockDim.x + threadIdx.x) >> 5;
    int lane = threadIdx.x & 31;
    if (n >= N) return;
    int head = lane >> 3;
    int c = lane * 4;

    float adh = __ldg(&g_ad[n * HEADS + head]);
    float4 acc = make_float4(0.f, 0.f, 0.f, 0.f);
    float den = 0.f;

    int e = g_rowptr[n];
    int end = e + g_deg[n];

    for (; e + 2 <= end; e += 2) {
        int s0 = __ldg(&g_csr_src[e]);
        int s1 = __ldg(&g_csr_src[e + 1]);
        float as0 = __ldg(&g_as[s0 * HEADS + head]);
        float as1 = __ldg(&g_as[s1 * HEADS + head]);
        float4 h0 = load_h4(&g_h[(size_t)s0 * F + c]);
        float4 h1 = load_h4(&g_h[(size_t)s1 * F + c]);
        float w0 = leaky_exp(as0 + adh);
        float w1 = leaky_exp(as1 + adh);
        den += w0 + w1;
        acc.x = fmaf(w0, h0.x, fmaf(w1, h1.x, acc.x));
        acc.y = fmaf(w0, h0.y, fmaf(w1, h1.y, acc.y));
        acc.z = fmaf(w0, h0.z, fmaf(w1, h1.z, acc.z));
        acc.w = fmaf(w0, h0.w, fmaf(w1, h1.w, acc.w));
    }
    if (e < end) {
        int s0 = __ldg(&g_csr_src[e]);
        float as0 = __ldg(&g_as[s0 * HEADS + head]);
        float4 h0 = load_h4(&g_h[(size_t)s0 * F + c]);
        float w0 = leaky_exp(as0 + adh);
        den += w0;
        acc.x = fmaf(w0, h0.x, acc.x);
        acc.y = fmaf(w0, h0.y, acc.y);
        acc.z = fmaf(w0, h0.z, acc.z);
        acc.w = fmaf(w0, h0.w, acc.w);
    }

    // self-loop
    float ws = leaky_exp(__ldg(&g_as[n * HEADS + head]) + adh);
    float4 hv = load_h4(&g_h[(size_t)n * F + c]);
    den += ws;
    acc.x = fmaf(ws, hv.x, acc.x);
    acc.y = fmaf(ws, hv.y, acc.y);
    acc.z = fmaf(ws, hv.z, acc.z);
    acc.w = fmaf(ws, hv.w, acc.w);

    float inv = 1.f / (den + 1e-16f);
    float4 bb = *(const float4*)&bias[c];
    float4 v;
    v.x = acc.x * inv + bb.x;
    v.y = acc.y * inv + bb.y;
    v.z = acc.z * inv + bb.z;
    v.w = acc.w * inv + bb.w;

    if (LAYER == 1) {
        v.x = v.x > 0.f ? v.x : expm1f(v.x);
        v.y = v.y > 0.f ? v.y : expm1f(v.y);
        v.z = v.z > 0.f ? v.z : expm1f(v.z);
        v.w = v.w > 0.f ? v.w : expm1f(v.w);
        uint2 packed;
        *reinterpret_cast<__half2*>(&packed.x) = __floats2half2_rn(v.x, v.y);
        *reinterpret_cast<__half2*>(&packed.y) = __floats2half2_rn(v.z, v.w);
        *(uint2*)&g_x2[(size_t)n * F + c] = packed;
    } else {
        *(float4*)&out[(size_t)n * F + c] = v;
        if (write_splits) {
            int off = c & 31;
            *(float4*)&out[(size_t)N * F + (size_t)head * N * 32 + (size_t)n * 32 + off] = v;
        }
    }
}

// ---------------- launch ----------------------------------------------------
extern "C" void kernel_launch(void* const* d_in, const int* in_sizes, int n_in,
                              void* d_out, int out_size) {
    const float* x   = (const float*)d_in[0];
    const int*   ei  = (const int*)d_in[1];
    const float* W1  = (const float*)d_in[2];
    const float* as1 = (const float*)d_in[3];
    const float* ad1 = (const float*)d_in[4];
    const float* b1  = (const float*)d_in[5];
    const float* W2  = (const float*)d_in[6];
    const float* as2 = (const float*)d_in[7];
    const float* ad2 = (const float*)d_in[8];
    const float* b2  = (const float*)d_in[9];

    int N = in_sizes[0] / F;
    int E = in_sizes[1] / 2;
    float* out = (float*)d_out;
    int write_splits = (out_size >= N * F * 2) ? 1 : 0;

    __half* p_x2 = nullptr;
    cudaGetSymbolAddress((void**)&p_x2, g_x2);

    const int SMEM_BYTES = (128 * XS_STRIDE + 128 * WS_STRIDE) * 4;
    cudaFuncSetAttribute(gemm_tf32_kernel<float>,
                         cudaFuncAttributeMaxDynamicSharedMemorySize, SMEM_BYTES);
    cudaFuncSetAttribute(gemm_tf32_kernel<__half>,
                         cudaFuncAttributeMaxDynamicSharedMemorySize, SMEM_BYTES);

    int gb = (N + 127) / 128;
    int wb = (N * 32 + 255) / 256;
    int nb1024 = (N + 1023) / 1024;

    // ---- CSR build (once, shared by both layers) ----
    zero_deg_kernel<<<(N + 255) / 256, 256>>>(N);
    deg_kernel<<<(E + 255) / 256, 256>>>(ei, E);
    scan1_kernel<<<nb1024, 1024>>>(N);
    scan3_kernel<<<nb1024, 1024>>>(N);
    scatter_kernel<<<(E + 255) / 256, 256>>>(ei, E);

    // ---- layer 1 ----
    gemm_tf32_kernel<float><<<gb, 256, SMEM_BYTES>>>(x, W1, as1, ad1, N);
    aggregate_kernel<1><<<wb, 256>>>(b1, out, N, 0);

    // ---- layer 2 ----
    gemm_tf32_kernel<__half><<<gb, 256, SMEM_BYTES>>>(p_x2, W2, as2, ad2, N);
    aggregate_kernel<2><<<wb, 256>>>(b2, out, N, write_splits);
}